// round 4
// baseline (speedup 1.0000x reference)
#include <cuda_runtime.h>

// ---------------- NAVAR dims ----------------
#define ND      2
#define NS      4
#define NV      12
#define HID     16
#define GROUPS  96
#define KS      4
#define T       2048
#define BATCH   8

// ---------------- tiling ----------------
#define TT      228              // output timesteps per tile
#define HALO    28               // 3 + 3*(1+2+4)
#define LL      (TT + HALO)      // 256 local positions
#define PITCH   260              // row pitch (floats), multiple of 4
#define NTHREADS 256
#define NTILES  9
#define PRED_ELEMS (BATCH*ND*NS*NV*T)        // 1,572,864
#define GUARD   16               // floats of scratch before bufA (negative-j reads)

typedef unsigned long long u64;

// ---- packed f32x2 helpers (Blackwell) ----
__device__ __forceinline__ u64 pk2(float a, float b) {
    u64 r; asm("mov.b64 %0, {%1, %2};" : "=l"(r) : "f"(a), "f"(b)); return r;
}
__device__ __forceinline__ u64 dup2f(float a) {
    u64 r; asm("mov.b64 %0, {%1, %1};" : "=l"(r) : "f"(a)); return r;
}
__device__ __forceinline__ void fma2(u64 &d, u64 a, u64 b) {
    asm("fma.rn.f32x2 %0, %1, %2, %0;" : "+l"(d) : "l"(a), "l"(b));
}
__device__ __forceinline__ void unpk(u64 v, float &lo, float &hi) {
    asm("mov.b64 {%0, %1}, %2;" : "=f"(lo), "=f"(hi) : "l"(v));
}

struct __align__(16) Smem {
    float bufs[GUARD + 2 * HID * PITCH]; // bufA, bufB back-to-back
    float xsb[4 + PITCH];                // 4-float guard for xs[j-3]
    u64   whp[HID * 8 * 4];              // L1 weights, co-paired: (ci, co-pair, tap)
    u64   whd[HID * HID * KS];           // L2/L3 weights, duplicated: (ci, co, tap)->(w,w)
    u64   woutp[HID * 6];                // output weights packed over dst pairs
    u64   boutp[6];
    float w_in[HID * KS];
    float b_in[HID];
    float b_h[3 * HID];
};  // ~48.0 KB

// ---- L1 hidden conv (D=1): co-paired scheme ----
// warp: cg=wid>>2 -> co 8*cg..8*cg+7 (4 pairs); tq=wid&3 -> j1=tq*64+lane, j2=j1+32
template<int D, int S>
__device__ __forceinline__ void hidden_cp(
    const float* __restrict__ in, float* __restrict__ out,
    const u64* __restrict__ wp, const float* __restrict__ bl,
    int gt0, int lane, int wid)
{
    const int cg = wid >> 2;
    const int tq = wid & 3;
    const int j1 = tq * 64 + lane;
    const int j2 = j1 + 32;

    u64 acc[4][2];
    #pragma unroll
    for (int p = 0; p < 4; p++) {
        u64 bp = pk2(bl[cg * 8 + 2 * p], bl[cg * 8 + 2 * p + 1]);
        acc[p][0] = bp; acc[p][1] = bp;
    }

    #pragma unroll 2
    for (int ci = 0; ci < HID; ci++) {
        const float* row = in + ci * PITCH;
        u64 vda[4], vdb[4];
        #pragma unroll
        for (int k = 0; k < 4; k++) {
            vda[k] = dup2f(row[j1 + (k - 3) * D]);
            vdb[k] = dup2f(row[j2 + (k - 3) * D]);
        }
        const ulonglong2* w2 = (const ulonglong2*)(wp + ci * 32 + cg * 16);
        #pragma unroll
        for (int p = 0; p < 4; p++) {
            ulonglong2 wa = w2[2 * p], wb = w2[2 * p + 1];
            fma2(acc[p][0], wa.x, vda[0]); fma2(acc[p][1], wa.x, vdb[0]);
            fma2(acc[p][0], wa.y, vda[1]); fma2(acc[p][1], wa.y, vdb[1]);
            fma2(acc[p][0], wb.x, vda[2]); fma2(acc[p][1], wb.x, vdb[2]);
            fma2(acc[p][0], wb.y, vda[3]); fma2(acc[p][1], wb.y, vdb[3]);
        }
    }

    #pragma unroll
    for (int p = 0; p < 4; p++) {
        const int co0 = cg * 8 + 2 * p;
        float a0, a1, c0, c1;
        unpk(acc[p][0], a0, a1);
        unpk(acc[p][1], c0, c1);
        if (j1 >= S) {
            bool z = (gt0 + j1) < 0;
            out[co0 * PITCH + j1]       = z ? 0.f : fmaxf(a0, 0.f);
            out[(co0 + 1) * PITCH + j1] = z ? 0.f : fmaxf(a1, 0.f);
        }
        {
            bool z = (gt0 + j2) < 0;
            out[co0 * PITCH + j2]       = z ? 0.f : fmaxf(c0, 0.f);
            out[(co0 + 1) * PITCH + j2] = z ? 0.f : fmaxf(c1, 0.f);
        }
    }
}

// ---- L2/L3 hidden conv (even D): j-paired scheme, zero packing movs ----
// thread: co = tid>>4, jblk = tid&15, j in [16*jblk, 16*jblk+15].
// acc[jp] packs (out[j0+2jp], out[j0+2jp+1]); data pairs come directly from
// aligned 16B loads (window starts at j0-AOFF, 16B aligned). Tap k uses pair
// index jp + (AOFF + (k-3)*D)/2.
template<int D, int S, int AOFF, int NLD>
__device__ __forceinline__ void hidden_jp(
    const float* __restrict__ in, float* __restrict__ out,
    const u64* __restrict__ wd, const float* __restrict__ bl,
    int gt0, int tid)
{
    const int co   = tid >> 4;
    const int jblk = tid & 15;
    const int j0   = jblk << 4;
    if (j0 + 15 < S) return;          // fully invalid block

    u64 acc[8];
    {
        u64 bp = dup2f(bl[co]);
        #pragma unroll
        for (int jp = 0; jp < 8; jp++) acc[jp] = bp;
    }

    #pragma unroll 2
    for (int ci = 0; ci < HID; ci++) {
        // 4 duplicated weights for (ci, co): 2x LDS.128
        const ulonglong2* w2 = (const ulonglong2*)(wd + ((ci << 4) + co) * 4);
        ulonglong2 wa = w2[0], wb = w2[1];

        // data window [j0-AOFF, j0+15], NLD aligned 16B loads -> 2*NLD pairs
        u64 pr[2 * NLD];
        const ulonglong2* pp = (const ulonglong2*)(in + ci * PITCH + j0 - AOFF);
        #pragma unroll
        for (int q = 0; q < NLD; q++) {
            ulonglong2 t = pp[q];
            pr[2 * q] = t.x; pr[2 * q + 1] = t.y;
        }

        #pragma unroll
        for (int jp = 0; jp < 8; jp++) {
            fma2(acc[jp], wa.x, pr[jp + (AOFF + (0 - 3) * D) / 2]);
            fma2(acc[jp], wa.y, pr[jp + (AOFF + (1 - 3) * D) / 2]);
            fma2(acc[jp], wb.x, pr[jp + (AOFF + (2 - 3) * D) / 2]);
            fma2(acc[jp], wb.y, pr[jp + (AOFF + (3 - 3) * D) / 2]);
        }
    }

    float* orow = out + co * PITCH;
    #pragma unroll
    for (int jp = 0; jp < 8; jp++) {
        int j = j0 + 2 * jp;
        if (j >= S) {
            float lo, hi; unpk(acc[jp], lo, hi);
            float v0 = ((gt0 + j)     < 0) ? 0.f : fmaxf(lo, 0.f);
            float v1 = ((gt0 + j + 1) < 0) ? 0.f : fmaxf(hi, 0.f);
            *(float2*)(orow + j) = make_float2(v0, v1);
        }
    }
}

__global__ void __launch_bounds__(NTHREADS, 3)
navar_main_kernel(const float* __restrict__ x,
                  const float* __restrict__ w_in, const float* __restrict__ b_in,
                  const float* __restrict__ w_h,  const float* __restrict__ b_h,
                  const float* __restrict__ w_out,const float* __restrict__ b_out,
                  float* __restrict__ out_contrib)
{
    __shared__ Smem s;
    float* bufA = s.bufs + GUARD;
    float* bufB = bufA + HID * PITCH;
    float* xs   = s.xsb + 4;

    const int tile = blockIdx.x;
    const int g    = blockIdx.y;
    const int b    = blockIdx.z;
    const int t0   = tile * TT;
    const int gt0  = t0 - HALO;
    const int tid  = threadIdx.x;
    const int lane = tid & 31;
    const int wid  = tid >> 5;

    // ---- stage x tile + all small params + L1 (packed) + L2 (dup'd) weights ----
    const float* xg = x + ((size_t)b * GROUPS + g) * T;
    for (int j = tid; j < PITCH; j += NTHREADS) {
        int gt = gt0 + j;
        xs[j] = (gt >= 0 && gt < T) ? xg[gt] : 0.f;
    }
    if (tid < HID * KS) s.w_in[tid] = w_in[g * HID * KS + tid];
    if (tid < HID)      s.b_in[tid] = b_in[g * HID + tid];
    for (int i = tid; i < 3 * HID; i += NTHREADS) {
        int L = i >> 4, co = i & 15;
        s.b_h[i] = b_h[L * GROUPS * HID + g * HID + co];
    }
    for (int i = tid; i < HID * 6 * 2; i += NTHREADS) {
        int half = i & 1, dp = (i >> 1) % 6, ci = (i >> 1) / 6;
        ((float*)s.woutp)[i] = w_out[((size_t)g * NV + 2 * dp + half) * HID + ci];
    }
    if (tid < 12) {
        int half = tid & 1, dp = tid >> 1;
        ((float*)s.boutp)[tid] = b_out[g * NV + 2 * dp + half];
    }
    // L1 packed weights: whp[(ci*8 + pg)*4 + k] = (w[2pg][ci][k], w[2pg+1][ci][k])
    {
        const float* wsrc = w_h + ((size_t)g * HID) * (HID * KS);   // layer 0
        float* wdst = (float*)s.whp;
        for (int i = tid; i < HID * HID * KS; i += NTHREADS) {
            int half = i & 1, k = (i >> 1) & 3, pg = (i >> 3) & 7, ci = i >> 6;
            wdst[i] = wsrc[((2 * pg + half) * HID + ci) * KS + k];
        }
    }
    // L2 duplicated weights: whd[(ci*16+co)*4 + k] = dup(w)
    {
        const float* wsrc = w_h + ((size_t)GROUPS * HID + (size_t)g * HID) * (HID * KS);
        #pragma unroll
        for (int r = 0; r < 4; r++) {
            int i = tid + r * NTHREADS;       // 0..1023
            int k = i & 3, co = (i >> 2) & 15, ci = i >> 6;
            float v = wsrc[(co * HID + ci) * KS + k];
            ((float2*)s.whd)[i] = make_float2(v, v);
        }
    }
    // prefetch L3 weights into registers (store after L2 compute)
    float wpref[4];
    {
        const float* wsrc = w_h + ((size_t)2 * GROUPS * HID + (size_t)g * HID) * (HID * KS);
        #pragma unroll
        for (int r = 0; r < 4; r++) {
            int i = tid + r * NTHREADS;
            int k = i & 3, co = (i >> 2) & 15, ci = i >> 6;
            wpref[r] = wsrc[(co * HID + ci) * KS + k];
        }
    }
    __syncthreads();

    // ---- input conv 1 -> HID (thread = timestep j) -> bufA ----
    {
        const int j = tid;
        float xv0 = xs[j - 3], xv1 = xs[j - 2], xv2 = xs[j - 1], xv3 = xs[j];
        const bool neg = (gt0 + j) < 0;
        #pragma unroll
        for (int co = 0; co < HID; co++) {
            float4 w = *(const float4*)(s.w_in + co * 4);
            float a = s.b_in[co];
            a = fmaf(w.x, xv0, a); a = fmaf(w.y, xv1, a);
            a = fmaf(w.z, xv2, a); a = fmaf(w.w, xv3, a);
            bufA[co * PITCH + j] = neg ? 0.f : fmaxf(a, 0.f);
        }
    }
    __syncthreads();

    // ---- L1: D=1, bufA -> bufB (co-paired) ----
    hidden_cp<1, 8>(bufA, bufB, s.whp, s.b_h, gt0, lane, wid);
    __syncthreads();

    // ---- L2: D=2, bufB -> bufA (j-paired, AOFF=8, 6 loads) ----
    hidden_jp<2, 16, 8, 6>(bufB, bufA, s.whd, s.b_h + HID, gt0, tid);
    __syncthreads();

    // ---- restage whd with L3 weights from prefetched regs ----
    #pragma unroll
    for (int r = 0; r < 4; r++) {
        int i = tid + r * NTHREADS;
        ((float2*)s.whd)[i] = make_float2(wpref[r], wpref[r]);
    }
    __syncthreads();

    // ---- L3: D=4, bufA -> bufB (j-paired, AOFF=12, 7 loads) ----
    hidden_jp<4, 28, 12, 7>(bufA, bufB, s.whd, s.b_h + 2 * HID, gt0, tid);
    __syncthreads();

    // ---- 1x1 output conv: thread = timestep, 12 dst as 6 packed pairs ----
    {
        const int dd  = g / (NS * NV);
        const int rem = g % (NS * NV);
        const int ss  = rem / NV;
        const int src = rem % NV;
        const size_t cbase = ((size_t)((b * ND + dd) * NS + ss) * NV * NV + src) * T;

        const int trel = tid;
        const int gt   = t0 + trel;
        const bool act = (trel < TT) && (gt < T);
        const int jc   = act ? (HALO + trel) : HALO;

        u64 a6[6];
        #pragma unroll
        for (int dp = 0; dp < 6; dp++) a6[dp] = s.boutp[dp];

        #pragma unroll
        for (int ci = 0; ci < HID; ci++) {
            u64 hd = dup2f(bufB[ci * PITCH + jc]);
            const ulonglong2* w2 = (const ulonglong2*)(s.woutp + ci * 6);
            ulonglong2 wA = w2[0], wB = w2[1], wC = w2[2];
            fma2(a6[0], wA.x, hd); fma2(a6[1], wA.y, hd);
            fma2(a6[2], wB.x, hd); fma2(a6[3], wB.y, hd);
            fma2(a6[4], wC.x, hd); fma2(a6[5], wC.y, hd);
        }
        if (act) {
            #pragma unroll
            for (int dp = 0; dp < 6; dp++) {
                float lo, hi; unpk(a6[dp], lo, hi);
                out_contrib[cbase + (size_t)(2 * dp)     * NV * T + gt] = lo;
                out_contrib[cbase + (size_t)(2 * dp + 1) * NV * T + gt] = hi;
            }
        }
    }
}

// prediction[b,dd,ss,v,t] = sum_src contrib[b,dd,ss,v,src,t] + biases[dd,ss,v]
__global__ void __launch_bounds__(256)
navar_pred_kernel(const float4* __restrict__ contrib4,
                  const float* __restrict__ biases,
                  float4* __restrict__ pred4)
{
    int idx = blockIdx.x * blockDim.x + threadIdx.x;
    if (idx >= PRED_ELEMS / 4) return;
    int t4 = idx & (T / 4 - 1);
    int r  = idx >> 9;                 // T/4 = 512
    float bsc = biases[r % (ND * NS * NV)];
    const float4* cp = contrib4 + (size_t)r * NV * (T / 4) + t4;
    float4 acc = make_float4(bsc, bsc, bsc, bsc);
    #pragma unroll
    for (int sI = 0; sI < NV; sI++) {
        float4 v = cp[(size_t)sI * (T / 4)];
        acc.x += v.x; acc.y += v.y; acc.z += v.z; acc.w += v.w;
    }
    pred4[idx] = acc;
}

extern "C" void kernel_launch(void* const* d_in, const int* in_sizes, int n_in,
                              void* d_out, int out_size)
{
    const float* x      = (const float*)d_in[0];
    const float* w_in   = (const float*)d_in[1];
    const float* b_in   = (const float*)d_in[2];
    const float* w_h    = (const float*)d_in[3];
    const float* b_h    = (const float*)d_in[4];
    const float* w_out  = (const float*)d_in[5];
    const float* b_out  = (const float*)d_in[6];
    const float* biases = (const float*)d_in[7];

    float* out     = (float*)d_out;
    float* pred    = out;                     // (B,ND,NS,NV,T)
    float* contrib = out + PRED_ELEMS;        // (B,ND,NS,NV,NV,T)

    dim3 grid(NTILES, GROUPS, BATCH);
    navar_main_kernel<<<grid, NTHREADS>>>(x, w_in, b_in, w_h, b_h, w_out, b_out, contrib);
    navar_pred_kernel<<<(PRED_ELEMS / 4 + 255) / 256, 256>>>(
        (const float4*)contrib, biases, (float4*)pred);
}

// round 5
// speedup vs baseline: 2.6211x; 2.6211x over previous
#include <cuda_runtime.h>

// ---------------- NAVAR dims ----------------
#define ND      2
#define NS      4
#define NV      12
#define HID     16
#define GROUPS  96
#define KS      4
#define T       2048
#define BATCH   8

// ---------------- tiling ----------------
#define TT      228              // output timesteps per tile
#define HALO    28               // 3 + 3*(1+2+4)
#define LL      (TT + HALO)      // 256 local positions
#define PITCH   260              // row pitch (floats)
#define NTHREADS 256
#define NTILES  9
#define PRED_ELEMS (BATCH*ND*NS*NV*T)        // 1,572,864
#define GUARD   16               // floats of scratch before bufA (negative-j reads)

typedef unsigned long long u64;

// ---- packed f32x2 helpers (Blackwell) ----
__device__ __forceinline__ u64 pk2(float a, float b) {
    u64 r; asm("mov.b64 %0, {%1, %2};" : "=l"(r) : "f"(a), "f"(b)); return r;
}
__device__ __forceinline__ u64 dup2f(float a) {
    u64 r; asm("mov.b64 %0, {%1, %1};" : "=l"(r) : "f"(a)); return r;
}
__device__ __forceinline__ void fma2(u64 &d, u64 a, u64 b) {
    asm("fma.rn.f32x2 %0, %1, %2, %0;" : "+l"(d) : "l"(a), "l"(b));
}
__device__ __forceinline__ void unpk(u64 v, float &lo, float &hi) {
    asm("mov.b64 {%0, %1}, %2;" : "=f"(lo), "=f"(hi) : "l"(v));
}

struct __align__(16) Smem {
    float bufs[GUARD + 2 * HID * PITCH]; // bufA, bufB back-to-back   33,344 B
    float xsb[4 + PITCH];                //                             1,056 B
    u64   whp[3][HID * 8 * KS];          // all 3 layers co-paired     12,288 B
    u64   woutp[HID * 6];                //                               768 B
    u64   boutp[6];                      //                                48 B
    float w_in[HID * KS];                //                               256 B
    float b_in[HID];                     //                                64 B
    float b_h[3 * HID];                  //                               192 B
};  // 48,016 B < 48 KB static limit; x3 CTAs = 144 KB/SM

// ---- hidden conv HID->HID dilation D, co-paired (proven R3 scheme) ----
// warp: cg=wid>>2 -> co 8*cg..8*cg+7 (4 packed pairs); tq=wid&3 -> j1=tq*64+lane,
// j2=j1+32.  Lane->j contiguous: all data LDS conflict-free, weights broadcast.
template<int D, int S>
__device__ __forceinline__ void hidden_cp(
    const float* __restrict__ in, float* __restrict__ out,
    const u64* __restrict__ wp, const float* __restrict__ bl,
    int gt0, int lane, int wid)
{
    const int cg = wid >> 2;
    const int tq = wid & 3;
    const int j1 = tq * 64 + lane;
    const int j2 = j1 + 32;

    u64 acc[4][2];
    #pragma unroll
    for (int p = 0; p < 4; p++) {
        u64 bp = pk2(bl[cg * 8 + 2 * p], bl[cg * 8 + 2 * p + 1]);
        acc[p][0] = bp; acc[p][1] = bp;
    }

    #pragma unroll 2
    for (int ci = 0; ci < HID; ci++) {
        const float* row = in + ci * PITCH;
        u64 vda[4], vdb[4];
        #pragma unroll
        for (int k = 0; k < 4; k++) {
            vda[k] = dup2f(row[j1 + (k - 3) * D]);
            vdb[k] = dup2f(row[j2 + (k - 3) * D]);
        }
        const ulonglong2* w2 = (const ulonglong2*)(wp + ci * 32 + cg * 16);
        #pragma unroll
        for (int p = 0; p < 4; p++) {
            ulonglong2 wa = w2[2 * p], wb = w2[2 * p + 1];
            fma2(acc[p][0], wa.x, vda[0]); fma2(acc[p][1], wa.x, vdb[0]);
            fma2(acc[p][0], wa.y, vda[1]); fma2(acc[p][1], wa.y, vdb[1]);
            fma2(acc[p][0], wb.x, vda[2]); fma2(acc[p][1], wb.x, vdb[2]);
            fma2(acc[p][0], wb.y, vda[3]); fma2(acc[p][1], wb.y, vdb[3]);
        }
    }

    #pragma unroll
    for (int p = 0; p < 4; p++) {
        const int co0 = cg * 8 + 2 * p;
        float a0, a1, c0, c1;
        unpk(acc[p][0], a0, a1);
        unpk(acc[p][1], c0, c1);
        if (j1 >= S) {
            bool z = (gt0 + j1) < 0;
            out[co0 * PITCH + j1]       = z ? 0.f : fmaxf(a0, 0.f);
            out[(co0 + 1) * PITCH + j1] = z ? 0.f : fmaxf(a1, 0.f);
        }
        {
            bool z = (gt0 + j2) < 0;
            out[co0 * PITCH + j2]       = z ? 0.f : fmaxf(c0, 0.f);
            out[(co0 + 1) * PITCH + j2] = z ? 0.f : fmaxf(c1, 0.f);
        }
    }
}

__global__ void __launch_bounds__(NTHREADS, 3)
navar_main_kernel(const float* __restrict__ x,
                  const float* __restrict__ w_in, const float* __restrict__ b_in,
                  const float* __restrict__ w_h,  const float* __restrict__ b_h,
                  const float* __restrict__ w_out,const float* __restrict__ b_out,
                  float* __restrict__ out_contrib)
{
    __shared__ Smem s;
    float* bufA = s.bufs + GUARD;
    float* bufB = bufA + HID * PITCH;
    float* xs   = s.xsb + 4;

    const int tile = blockIdx.x;
    const int g    = blockIdx.y;
    const int b    = blockIdx.z;
    const int t0   = tile * TT;
    const int gt0  = t0 - HALO;
    const int tid  = threadIdx.x;
    const int lane = tid & 31;
    const int wid  = tid >> 5;

    // ---- stage x tile + all params (all 3 hidden layers prestaged) ----
    const float* xg = x + ((size_t)b * GROUPS + g) * T;
    for (int j = tid; j < PITCH; j += NTHREADS) {
        int gt = gt0 + j;
        xs[j] = (gt >= 0 && gt < T) ? xg[gt] : 0.f;
    }
    if (tid < HID * KS) s.w_in[tid] = w_in[g * HID * KS + tid];
    if (tid < HID)      s.b_in[tid] = b_in[g * HID + tid];
    for (int i = tid; i < 3 * HID; i += NTHREADS) {
        int L = i >> 4, co = i & 15;
        s.b_h[i] = b_h[L * GROUPS * HID + g * HID + co];
    }
    for (int i = tid; i < HID * 6 * 2; i += NTHREADS) {
        int half = i & 1, dp = (i >> 1) % 6, ci = (i >> 1) / 6;
        ((float*)s.woutp)[i] = w_out[((size_t)g * NV + 2 * dp + half) * HID + ci];
    }
    if (tid < 12) {
        int half = tid & 1, dp = tid >> 1;
        ((float*)s.boutp)[tid] = b_out[g * NV + 2 * dp + half];
    }
    // hidden weights, co-paired: whp[L][(ci*8+pg)*4+k] = (w[2pg][ci][k], w[2pg+1][ci][k])
    #pragma unroll 1
    for (int L = 0; L < 3; L++) {
        const float* wsrc = w_h + ((size_t)L * GROUPS * HID + (size_t)g * HID) * (HID * KS);
        float* wdst = (float*)s.whp[L];
        #pragma unroll
        for (int r = 0; r < 4; r++) {
            int i = tid + r * NTHREADS;       // 0..1023
            int half = i & 1, k = (i >> 1) & 3, pg = (i >> 3) & 7, ci = i >> 6;
            wdst[i] = wsrc[((2 * pg + half) * HID + ci) * KS + k];
        }
    }
    __syncthreads();

    // ---- input conv 1 -> HID (thread = timestep j) -> bufA ----
    {
        const int j = tid;
        float xv0 = xs[j - 3], xv1 = xs[j - 2], xv2 = xs[j - 1], xv3 = xs[j];
        const bool neg = (gt0 + j) < 0;
        #pragma unroll
        for (int co = 0; co < HID; co++) {
            float4 w = *(const float4*)(s.w_in + co * 4);
            float a = s.b_in[co];
            a = fmaf(w.x, xv0, a); a = fmaf(w.y, xv1, a);
            a = fmaf(w.z, xv2, a); a = fmaf(w.w, xv3, a);
            bufA[co * PITCH + j] = neg ? 0.f : fmaxf(a, 0.f);
        }
    }
    __syncthreads();

    hidden_cp<1,  8>(bufA, bufB, s.whp[0], s.b_h,           gt0, lane, wid);
    __syncthreads();
    hidden_cp<2, 16>(bufB, bufA, s.whp[1], s.b_h + HID,     gt0, lane, wid);
    __syncthreads();
    hidden_cp<4, 28>(bufA, bufB, s.whp[2], s.b_h + 2 * HID, gt0, lane, wid);
    __syncthreads();

    // ---- 1x1 output conv: thread = timestep, 12 dst as 6 packed pairs ----
    {
        const int dd  = g / (NS * NV);
        const int rem = g % (NS * NV);
        const int ss  = rem / NV;
        const int src = rem % NV;
        const size_t cbase = ((size_t)((b * ND + dd) * NS + ss) * NV * NV + src) * T;

        const int trel = tid;
        const int gt   = t0 + trel;
        const bool act = (trel < TT) && (gt < T);
        const int jc   = act ? (HALO + trel) : HALO;

        u64 a6[6];
        #pragma unroll
        for (int dp = 0; dp < 6; dp++) a6[dp] = s.boutp[dp];

        #pragma unroll
        for (int ci = 0; ci < HID; ci++) {
            u64 hd = dup2f(bufB[ci * PITCH + jc]);
            const ulonglong2* w2 = (const ulonglong2*)(s.woutp + ci * 6);
            ulonglong2 wA = w2[0], wB = w2[1], wC = w2[2];
            fma2(a6[0], wA.x, hd); fma2(a6[1], wA.y, hd);
            fma2(a6[2], wB.x, hd); fma2(a6[3], wB.y, hd);
            fma2(a6[4], wC.x, hd); fma2(a6[5], wC.y, hd);
        }
        if (act) {
            #pragma unroll
            for (int dp = 0; dp < 6; dp++) {
                float lo, hi; unpk(a6[dp], lo, hi);
                out_contrib[cbase + (size_t)(2 * dp)     * NV * T + gt] = lo;
                out_contrib[cbase + (size_t)(2 * dp + 1) * NV * T + gt] = hi;
            }
        }
    }
}

// prediction[b,dd,ss,v,t] = sum_src contrib[b,dd,ss,v,src,t] + biases[dd,ss,v]
__global__ void __launch_bounds__(256)
navar_pred_kernel(const float4* __restrict__ contrib4,
                  const float* __restrict__ biases,
                  float4* __restrict__ pred4)
{
    int idx = blockIdx.x * blockDim.x + threadIdx.x;
    if (idx >= PRED_ELEMS / 4) return;
    int t4 = idx & (T / 4 - 1);
    int r  = idx >> 9;                 // T/4 = 512
    float bsc = biases[r % (ND * NS * NV)];
    const float4* cp = contrib4 + (size_t)r * NV * (T / 4) + t4;
    float4 acc = make_float4(bsc, bsc, bsc, bsc);
    #pragma unroll
    for (int sI = 0; sI < NV; sI++) {
        float4 v = cp[(size_t)sI * (T / 4)];
        acc.x += v.x; acc.y += v.y; acc.z += v.z; acc.w += v.w;
    }
    pred4[idx] = acc;
}

extern "C" void kernel_launch(void* const* d_in, const int* in_sizes, int n_in,
                              void* d_out, int out_size)
{
    const float* x      = (const float*)d_in[0];
    const float* w_in   = (const float*)d_in[1];
    const float* b_in   = (const float*)d_in[2];
    const float* w_h    = (const float*)d_in[3];
    const float* b_h    = (const float*)d_in[4];
    const float* w_out  = (const float*)d_in[5];
    const float* b_out  = (const float*)d_in[6];
    const float* biases = (const float*)d_in[7];

    float* out     = (float*)d_out;
    float* pred    = out;                     // (B,ND,NS,NV,T)
    float* contrib = out + PRED_ELEMS;        // (B,ND,NS,NV,NV,T)

    dim3 grid(NTILES, GROUPS, BATCH);
    navar_main_kernel<<<grid, NTHREADS>>>(x, w_in, b_in, w_h, b_h, w_out, b_out, contrib);
    navar_pred_kernel<<<(PRED_ELEMS / 4 + 255) / 256, 256>>>(
        (const float4*)contrib, biases, (float4*)pred);
}